// round 13
// baseline (speedup 1.0000x reference)
#include <cuda_runtime.h>
#include <math.h>

#define T_LEN 2048
#define B_SZ  64
#define I_SZ  256
#define H_SZ  256

#define NGRP 32
#define CPG  8     // CTAs per group = cluster size
#define NB   2     // batches per group

typedef unsigned long long u64;

__device__ __forceinline__ void fma2(u64 &d, u64 a, u64 b) {
    asm("fma.rn.f32x2 %0, %1, %2, %0;" : "+l"(d) : "l"(a), "l"(b));
}
__device__ __forceinline__ float2 u2f(u64 v) {
    float2 r; asm("mov.b64 {%0, %1}, %2;" : "=f"(r.x), "=f"(r.y) : "l"(v)); return r;
}
__device__ __forceinline__ u64 dup2(float x) {
    u64 r; asm("mov.b64 %0, {%1, %1};" : "=l"(r) : "f"(x)); return r;
}
__device__ __forceinline__ unsigned smem_u32(const void* p) {
    unsigned a;
    asm("{ .reg .u64 t; cvta.to.shared.u64 t, %1; cvt.u32.u64 %0, t; }" : "=r"(a) : "l"(p));
    return a;
}
// Fast sigmoid / tanh via ex2.approx + rcp.approx (rel err ~2^-22).
__device__ __forceinline__ float fast_sigmoid(float x) {
    x = fminf(fmaxf(x, -20.f), 20.f);
    float e, r;
    asm("ex2.approx.f32 %0, %1;" : "=f"(e) : "f"(-x * 1.4426950408889634f));
    asm("rcp.approx.f32 %0, %1;" : "=f"(r) : "f"(e + 1.0f));
    return r;
}
__device__ __forceinline__ float fast_tanh(float x) {
    x = fminf(fmaxf(x, -15.f), 15.f);
    float e, r;
    asm("ex2.approx.f32 %0, %1;" : "=f"(e) : "f"(x * 2.8853900817779268f));  // e^{2x}
    asm("rcp.approx.f32 %0, %1;" : "=f"(r) : "f"(e + 1.0f));
    return (e - 1.0f) * r;
}

// ---------------- scratch ----------------------------------------------------
__device__ float g_xfh[(size_t)T_LEN * B_SZ * 512];   // [t][b][0:256]=xf, [256:512]=xh

// ---------------- projection GEMM (double-buffered, f32x2) -------------------
__global__ __launch_bounds__(256) void proj_kernel(
    const float* __restrict__ seq,
    const float* __restrict__ Wf, const float* __restrict__ bf,
    const float* __restrict__ Wh, const float* __restrict__ bh)
{
    __shared__ float2 As2[2][8][130];
    __shared__ float  Bs[2][8][132];

    const int bm = blockIdx.x;
    const int bn = blockIdx.y;
    const float* __restrict__ W    = (bn < 2) ? Wf : Wh;
    const float* __restrict__ bias = (bn < 2) ? bf : bh;
    const int nb = (bn & 1) * 128;

    const int tid  = threadIdx.x;
    const int tx   = tid & 15;
    const int ty   = tid >> 4;
    const int arow = tid >> 1, acol = (tid & 1) * 4;
    const int brow = tid >> 5, bcol = (tid & 31) * 4;
    const size_t abase = (size_t)(bm * 128 + arow) * 256 + acol;

    u64 acc[8][4];
#pragma unroll
    for (int i = 0; i < 8; i++)
#pragma unroll
        for (int j = 0; j < 4; j++) acc[i][j] = 0ull;

    {
        float4 av = *(const float4*)&seq[abase];
        float4 bv = *(const float4*)&W[(size_t)brow * 256 + nb + bcol];
        As2[0][acol + 0][arow] = make_float2(av.x, av.x);
        As2[0][acol + 1][arow] = make_float2(av.y, av.y);
        As2[0][acol + 2][arow] = make_float2(av.z, av.z);
        As2[0][acol + 3][arow] = make_float2(av.w, av.w);
        *(float4*)&Bs[0][brow][bcol] = bv;
    }
    __syncthreads();

    for (int it = 0; it < 32; it++) {
        const int p = it & 1;
        float4 av, bv;
        if (it < 31) {
            const int k0 = (it + 1) * 8;
            av = *(const float4*)&seq[abase + k0];
            bv = *(const float4*)&W[(size_t)(k0 + brow) * 256 + nb + bcol];
        }
#pragma unroll
        for (int k = 0; k < 8; k++) {
            ulonglong2 a01 = *(const ulonglong2*)&As2[p][k][ty * 8 + 0];
            ulonglong2 a23 = *(const ulonglong2*)&As2[p][k][ty * 8 + 2];
            ulonglong2 a45 = *(const ulonglong2*)&As2[p][k][ty * 8 + 4];
            ulonglong2 a67 = *(const ulonglong2*)&As2[p][k][ty * 8 + 6];
            ulonglong2 b01 = *(const ulonglong2*)&Bs[p][k][tx * 8];
            ulonglong2 b23 = *(const ulonglong2*)&Bs[p][k][tx * 8 + 4];
            u64 ad[8] = {a01.x, a01.y, a23.x, a23.y, a45.x, a45.y, a67.x, a67.y};
#pragma unroll
            for (int i = 0; i < 8; i++) {
                fma2(acc[i][0], ad[i], b01.x);
                fma2(acc[i][1], ad[i], b01.y);
                fma2(acc[i][2], ad[i], b23.x);
                fma2(acc[i][3], ad[i], b23.y);
            }
        }
        if (it < 31) {
            const int np = p ^ 1;
            As2[np][acol + 0][arow] = make_float2(av.x, av.x);
            As2[np][acol + 1][arow] = make_float2(av.y, av.y);
            As2[np][acol + 2][arow] = make_float2(av.z, av.z);
            As2[np][acol + 3][arow] = make_float2(av.w, av.w);
            *(float4*)&Bs[np][brow][bcol] = bv;
        }
        __syncthreads();
    }

    float bb[8];
#pragma unroll
    for (int j = 0; j < 8; j++) bb[j] = bias[nb + tx * 8 + j];

#pragma unroll
    for (int i = 0; i < 8; i++) {
        size_t m = (size_t)bm * 128 + ty * 8 + i;
        float* op = &g_xfh[m * 512 + (size_t)bn * 128 + tx * 8];
        float2 c0 = u2f(acc[i][0]), c1 = u2f(acc[i][1]);
        float2 c2 = u2f(acc[i][2]), c3 = u2f(acc[i][3]);
        float4 v0, v1;
        v0.x = c0.x + bb[0]; v0.y = c0.y + bb[1];
        v0.z = c1.x + bb[2]; v0.w = c1.y + bb[3];
        v1.x = c2.x + bb[4]; v1.y = c2.y + bb[5];
        v1.z = c3.x + bb[6]; v1.w = c3.y + bb[7];
        *(float4*)&op[0] = v0;
        *(float4*)&op[4] = v1;
    }
}

// ---------------- persistent recurrence: 32 groups x 2 batches ---------------
// R12 protocol/transport. New: warp-0-only epilogue with register-direct
// st.async sends (no sOut staging, no second syncthreads); sRed is
// double-buffered (stride 20 -> aligned LDS.128 epilogue reads).
__global__ __launch_bounds__(256, 2) __cluster_dims__(CPG, 1, 1)
void rec_kernel(const float* __restrict__ Uf, const float* __restrict__ Uh,
                const float* __restrict__ pa, float* __restrict__ out)
{
    __shared__ float4 sHp[2][256];                     // 8 KB recv: [buf][k]=(h0,h0,h1,h1)
    __shared__ float  sRed[2][64 * 20];                // 10 KB: [buf][vc*20 + b*8 + w]
    __shared__ __align__(16) u64 mbar[2][CPG];         // per-buffer, per-source

    const int g   = blockIdx.x >> 3;                   // 0..31
    unsigned cgi;
    asm("mov.u32 %0, %%cluster_ctarank;" : "=r"(cgi));
    const int j0  = (int)cgi * 32;
    const int tid = threadIdx.x;
    const int w   = tid >> 5;
    const int l   = tid & 31;
    const int kb  = w * 32;
    const int vc0 = 2 * l;

    // Register-resident U as NATURAL (c0,c1) pairs: 32 x u64 per thread.
    const float* __restrict__ Usrc = (vc0 < 32) ? Uf : Uh;
    const int c0 = j0 + (vc0 & 31);
    u64 uu[32];
#pragma unroll
    for (int i = 0; i < 32; i++)
        uu[i] = *(const u64*)&Usrc[(size_t)(kb + i) * H_SZ + c0];
    const float aP = pa[0];

    const unsigned sH_a = smem_u32(&sHp[0][0]);
    const unsigned mb_a = smem_u32(&mbar[0][0]);

    // Zero buffer 0 (step-0 h = 0); init barriers; pre-post expects for buf 1.
    sHp[0][tid] = make_float4(0.f, 0.f, 0.f, 0.f);
    if (tid == 0) {
#pragma unroll
        for (int s = 0; s < 2 * CPG; s++)
            asm volatile("mbarrier.init.shared.b64 [%0], 1;"
                         :: "r"(mb_a + 8u * s) : "memory");
#pragma unroll
        for (int s = 0; s < CPG; s++)   // buffer 1 first fill (sent at end of t=0)
            asm volatile("mbarrier.arrive.expect_tx.shared.b64 _, [%0], %1;"
                         :: "r"(mb_a + 8u * (CPG + s)), "r"(512u) : "memory");
    }
    __syncthreads();
    asm volatile("barrier.cluster.arrive.aligned;" ::: "memory");
    asm volatile("barrier.cluster.wait.aligned;" ::: "memory");

    // All-rank remote addresses, staggered start (r -> rank (cgi+r)&7).
    unsigned rbase[CPG], rmb[CPG];
#pragma unroll
    for (int r = 0; r < CPG; r++) {
        const unsigned rr = (cgi + (unsigned)r) & 7u;
        asm("mapa.shared::cluster.u32 %0, %1, %2;" : "=r"(rbase[r]) : "r"(sH_a), "r"(rr));
        asm("mapa.shared::cluster.u32 %0, %1, %2;" : "=r"(rmb[r])  : "r"(mb_a), "r"(rr));
    }

    // Warp-0 epilogue: lane l owns column j0+l, BOTH batches.
    const size_t xstride = (size_t)B_SZ * 512;
    const size_t xoff0 = ((size_t)(g * NB + 0)) * 512 + j0 + l;
    const size_t xoff1 = ((size_t)(g * NB + 1)) * 512 + j0 + l;
    float xf0 = 0.f, xh0 = 0.f, xf1 = 0.f, xh1 = 0.f;
    if (w == 0) {
        xf0 = g_xfh[xoff0];       xh0 = g_xfh[xoff0 + 256];
        xf1 = g_xfh[xoff1];       xh1 = g_xfh[xoff1 + 256];
    }

    int par[2] = {0, 0};

    for (int t = 0; t < T_LEN; t++) {
        const int b  = t & 1;
        const int sb = b ^ 1;

        // Prefetch next step's xf/xh (warp 0; ~full step of latency cover).
        float xf0n = 0.f, xh0n = 0.f, xf1n = 0.f, xh1n = 0.f;
        if (w == 0) {
            const size_t tt = (t + 1 < T_LEN) ? (size_t)(t + 1) : (size_t)t;
            const float* xp = &g_xfh[tt * xstride];
            xf0n = xp[xoff0];  xh0n = xp[xoff0 + 256];
            xf1n = xp[xoff1];  xh1n = xp[xoff1 + 256];
        }

        if (t > 0) {   // warp w waits ONLY for its own source chunk
            const unsigned mb = mb_a + 8u * (unsigned)(b * CPG + w);
            asm volatile(
                "{\n\t .reg .pred p;\n\t"
                "LW%=:\n\t"
                "mbarrier.try_wait.parity.acquire.cluster.shared::cta.b64 p, [%0], %1, 0x989680;\n\t"
                "@!p bra LW%=;\n\t}"
                :: "r"(mb), "r"((unsigned)par[b]) : "memory");
            par[b] ^= 1;
        }

        const float4* __restrict__ hR = &sHp[b][0];

        u64 a0 = 0ull, a1 = 0ull;   // (c0,c1) partials for batch 0 / batch 1
#pragma unroll
        for (int i = 0; i < 32; i++) {
            ulonglong2 hp = *(const ulonglong2*)&hR[kb + i];  // (h0,h0),(h1,h1)
            fma2(a0, uu[i], hp.x);
            fma2(a1, uu[i], hp.y);
        }
        {
            float2 p0 = u2f(a0), p1 = u2f(a1);
            float* r0 = &sRed[b][vc0 * 20 + w];
            float* r1 = &sRed[b][(vc0 + 1) * 20 + w];
            r0[0] = p0.x;  r1[0] = p0.y;
            r0[8] = p1.x;  r1[8] = p1.y;
        }
        __syncthreads();   // partials visible to warp 0; all chunks arrived

        if (w == 0) {
            // Post expects for buffer b's NEXT fill (lanes 0-7), BEFORE sends.
            if (l < 8 && t < T_LEN - 2)
                asm volatile("mbarrier.arrive.expect_tx.shared.b64 _, [%0], %1;"
                             :: "r"(mb_a + 8u * (unsigned)(b * CPG + l)), "r"(512u)
                             : "memory");

            // Epilogue: column l, both batches. 16 contiguous floats per part.
            const float4* rf = (const float4*)&sRed[b][l * 20];
            const float4* rh = (const float4*)&sRed[b][(l + 32) * 20];
            float4 f0 = rf[0], f1 = rf[1], f2 = rf[2], f3 = rf[3];
            float4 h0 = rh[0], h1 = rh[1], h2 = rh[2], h3 = rh[3];
            float pf0 = ((f0.x + f0.y) + (f0.z + f0.w)) + ((f1.x + f1.y) + (f1.z + f1.w)) + xf0;
            float pf1 = ((f2.x + f2.y) + (f2.z + f2.w)) + ((f3.x + f3.y) + (f3.z + f3.w)) + xf1;
            float ph0 = ((h0.x + h0.y) + (h0.z + h0.w)) + ((h1.x + h1.y) + (h1.z + h1.w)) + xh0;
            float ph1 = ((h2.x + h2.y) + (h2.z + h2.w)) + ((h3.x + h3.y) + (h3.z + h3.w)) + xh1;

            const float* hold = (const float*)&hR[j0 + l];
            float ff0 = fast_sigmoid(pf0), ff1 = fast_sigmoid(pf1);
            float tn0 = fast_tanh(ph0),    tn1 = fast_tanh(ph1);
            float hv0 = ff0 * hold[0] + (1.0f - ff0) * tn0;
            float hv1 = ff1 * hold[2] + (1.0f - ff1) * tn1;
            hv0 = (hv0 >= 0.0f) ? hv0 : aP * hv0;
            hv1 = (hv1 >= 0.0f) ? hv1 : aP * hv1;

            __syncwarp();   // expect posts (lanes 0-7) ordered before sends

            if (t < T_LEN - 1) {
                const u64 p0 = dup2(hv0), p1 = dup2(hv1);   // (hv0,hv0,hv1,hv1)
                const unsigned doff = (unsigned)sb * 4096u + cgi * 512u
                                    + (unsigned)l * 16u;
                const unsigned mbo  = 8u * ((unsigned)sb * CPG + cgi);
#pragma unroll
                for (int r = 0; r < CPG; r++) {
                    asm volatile(
                        "st.async.shared::cluster.mbarrier::complete_tx::bytes.v2.b64 "
                        "[%0], {%1, %2}, [%3];"
                        :: "r"(rbase[r] + doff), "l"(p0), "l"(p1),
                           "r"(rmb[r] + mbo)
                        : "memory");
                }
            }
            // Global stores off the critical path.
            float* op = &out[(size_t)t * B_SZ * H_SZ + (size_t)(g * NB) * H_SZ + j0 + l];
            op[0]    = hv0;
            op[H_SZ] = hv1;
        }

        xf0 = xf0n; xh0 = xh0n; xf1 = xf1n; xh1 = xh1n;
    }

    asm volatile("barrier.cluster.arrive.aligned;" ::: "memory");
    asm volatile("barrier.cluster.wait.aligned;" ::: "memory");
    if (tid == 0) {   // leave raw memory for next graph replay's init
#pragma unroll
        for (int s = 0; s < 2 * CPG; s++)
            asm volatile("mbarrier.inval.shared.b64 [%0];"
                         :: "r"(mb_a + 8u * s) : "memory");
    }
}

// ---------------- launch ------------------------------------------------------
extern "C" void kernel_launch(void* const* d_in, const int* in_sizes, int n_in,
                              void* d_out, int out_size) {
    (void)in_sizes; (void)n_in; (void)out_size;
    const float* seq = (const float*)d_in[0];
    const float* Wf  = (const float*)d_in[1];
    const float* Uf  = (const float*)d_in[2];
    const float* bf  = (const float*)d_in[3];
    const float* Wh  = (const float*)d_in[4];
    const float* Uh  = (const float*)d_in[5];
    const float* bh  = (const float*)d_in[6];
    const float* pa  = (const float*)d_in[7];
    float* out = (float*)d_out;

    dim3 pgrid(T_LEN * B_SZ / 128, 4);
    proj_kernel<<<pgrid, 256>>>(seq, Wf, bf, Wh, bh);

    rec_kernel<<<NGRP * CPG, 256>>>(Uf, Uh, pa, out);
}

// round 15
// speedup vs baseline: 1.1534x; 1.1534x over previous
#include <cuda_runtime.h>
#include <math.h>

#define T_LEN 2048
#define B_SZ  64
#define I_SZ  256
#define H_SZ  256

#define NGRP 32
#define CPG  8     // CTAs per group = cluster size
#define NB   2     // batches per group

typedef unsigned long long u64;

__device__ __forceinline__ void fma2(u64 &d, u64 a, u64 b) {
    asm("fma.rn.f32x2 %0, %1, %2, %0;" : "+l"(d) : "l"(a), "l"(b));
}
__device__ __forceinline__ float2 u2f(u64 v) {
    float2 r; asm("mov.b64 {%0, %1}, %2;" : "=f"(r.x), "=f"(r.y) : "l"(v)); return r;
}
__device__ __forceinline__ unsigned smem_u32(const void* p) {
    unsigned a;
    asm("{ .reg .u64 t; cvta.to.shared.u64 t, %1; cvt.u32.u64 %0, t; }" : "=r"(a) : "l"(p));
    return a;
}
// Fast sigmoid / tanh via ex2.approx + rcp.approx (rel err ~2^-22).
__device__ __forceinline__ float fast_sigmoid(float x) {
    x = fminf(fmaxf(x, -20.f), 20.f);
    float e, r;
    asm("ex2.approx.f32 %0, %1;" : "=f"(e) : "f"(-x * 1.4426950408889634f));
    asm("rcp.approx.f32 %0, %1;" : "=f"(r) : "f"(e + 1.0f));
    return r;
}
__device__ __forceinline__ float fast_tanh(float x) {
    x = fminf(fmaxf(x, -15.f), 15.f);
    float e, r;
    asm("ex2.approx.f32 %0, %1;" : "=f"(e) : "f"(x * 2.8853900817779268f));  // e^{2x}
    asm("rcp.approx.f32 %0, %1;" : "=f"(r) : "f"(e + 1.0f));
    return (e - 1.0f) * r;
}

// ---------------- scratch ----------------------------------------------------
__device__ float g_xfh[(size_t)T_LEN * B_SZ * 512];   // [t][b][0:256]=xf, [256:512]=xh

// ---------------- projection GEMM (double-buffered, f32x2) -------------------
__global__ __launch_bounds__(256) void proj_kernel(
    const float* __restrict__ seq,
    const float* __restrict__ Wf, const float* __restrict__ bf,
    const float* __restrict__ Wh, const float* __restrict__ bh)
{
    __shared__ float2 As2[2][8][130];
    __shared__ float  Bs[2][8][132];

    const int bm = blockIdx.x;
    const int bn = blockIdx.y;
    const float* __restrict__ W    = (bn < 2) ? Wf : Wh;
    const float* __restrict__ bias = (bn < 2) ? bf : bh;
    const int nb = (bn & 1) * 128;

    const int tid  = threadIdx.x;
    const int tx   = tid & 15;
    const int ty   = tid >> 4;
    const int arow = tid >> 1, acol = (tid & 1) * 4;
    const int brow = tid >> 5, bcol = (tid & 31) * 4;
    const size_t abase = (size_t)(bm * 128 + arow) * 256 + acol;

    u64 acc[8][4];
#pragma unroll
    for (int i = 0; i < 8; i++)
#pragma unroll
        for (int j = 0; j < 4; j++) acc[i][j] = 0ull;

    {
        float4 av = *(const float4*)&seq[abase];
        float4 bv = *(const float4*)&W[(size_t)brow * 256 + nb + bcol];
        As2[0][acol + 0][arow] = make_float2(av.x, av.x);
        As2[0][acol + 1][arow] = make_float2(av.y, av.y);
        As2[0][acol + 2][arow] = make_float2(av.z, av.z);
        As2[0][acol + 3][arow] = make_float2(av.w, av.w);
        *(float4*)&Bs[0][brow][bcol] = bv;
    }
    __syncthreads();

    for (int it = 0; it < 32; it++) {
        const int p = it & 1;
        float4 av, bv;
        if (it < 31) {
            const int k0 = (it + 1) * 8;
            av = *(const float4*)&seq[abase + k0];
            bv = *(const float4*)&W[(size_t)(k0 + brow) * 256 + nb + bcol];
        }
#pragma unroll
        for (int k = 0; k < 8; k++) {
            ulonglong2 a01 = *(const ulonglong2*)&As2[p][k][ty * 8 + 0];
            ulonglong2 a23 = *(const ulonglong2*)&As2[p][k][ty * 8 + 2];
            ulonglong2 a45 = *(const ulonglong2*)&As2[p][k][ty * 8 + 4];
            ulonglong2 a67 = *(const ulonglong2*)&As2[p][k][ty * 8 + 6];
            ulonglong2 b01 = *(const ulonglong2*)&Bs[p][k][tx * 8];
            ulonglong2 b23 = *(const ulonglong2*)&Bs[p][k][tx * 8 + 4];
            u64 ad[8] = {a01.x, a01.y, a23.x, a23.y, a45.x, a45.y, a67.x, a67.y};
#pragma unroll
            for (int i = 0; i < 8; i++) {
                fma2(acc[i][0], ad[i], b01.x);
                fma2(acc[i][1], ad[i], b01.y);
                fma2(acc[i][2], ad[i], b23.x);
                fma2(acc[i][3], ad[i], b23.y);
            }
        }
        if (it < 31) {
            const int np = p ^ 1;
            As2[np][acol + 0][arow] = make_float2(av.x, av.x);
            As2[np][acol + 1][arow] = make_float2(av.y, av.y);
            As2[np][acol + 2][arow] = make_float2(av.z, av.z);
            As2[np][acol + 3][arow] = make_float2(av.w, av.w);
            *(float4*)&Bs[np][brow][bcol] = bv;
        }
        __syncthreads();
    }

    float bb[8];
#pragma unroll
    for (int j = 0; j < 8; j++) bb[j] = bias[nb + tx * 8 + j];

#pragma unroll
    for (int i = 0; i < 8; i++) {
        size_t m = (size_t)bm * 128 + ty * 8 + i;
        float* op = &g_xfh[m * 512 + (size_t)bn * 128 + tx * 8];
        float2 c0 = u2f(acc[i][0]), c1 = u2f(acc[i][1]);
        float2 c2 = u2f(acc[i][2]), c3 = u2f(acc[i][3]);
        float4 v0, v1;
        v0.x = c0.x + bb[0]; v0.y = c0.y + bb[1];
        v0.z = c1.x + bb[2]; v0.w = c1.y + bb[3];
        v1.x = c2.x + bb[4]; v1.y = c2.y + bb[5];
        v1.z = c3.x + bb[6]; v1.w = c3.y + bb[7];
        *(float4*)&op[0] = v0;
        *(float4*)&op[4] = v1;
    }
}

// ---------------- persistent recurrence: 32 groups x 2 batches ---------------
// R12 protocol/transport. Changes: sRed double-buffered by parity; warps 2-7
// free-run to their next mbarrier wait after the (all-warp) syncthreads;
// warps 0-1 finish the step behind a fixed-membership bar.sync 3,64 and
// split send duty (4 peers per warp).
__global__ __launch_bounds__(256, 2) __cluster_dims__(CPG, 1, 1)
void rec_kernel(const float* __restrict__ Uf, const float* __restrict__ Uh,
                const float* __restrict__ pa, float* __restrict__ out)
{
    __shared__ float4 sHp[2][256];                     // 8 KB recv: [buf][k]=(h0,h0,h1,h1)
    __shared__ float  sRed[2][64 * 17];                // 8.7 KB: [buf][vc*17 + b*8 + w]
    __shared__ __align__(16) float sOut[2][128];       // 1 KB staging: [buf][col*4+b*2+d]
    __shared__ __align__(16) u64 mbar[2][CPG];         // per-buffer, per-source

    const int g   = blockIdx.x >> 3;                   // 0..31
    unsigned cgi;
    asm("mov.u32 %0, %%cluster_ctarank;" : "=r"(cgi));
    const int j0  = (int)cgi * 32;
    const int tid = threadIdx.x;
    const int w   = tid >> 5;
    const int l   = tid & 31;
    const int kb  = w * 32;
    const int vc0 = 2 * l;

    // Register-resident U as NATURAL (c0,c1) pairs: 32 x u64 per thread.
    const float* __restrict__ Usrc = (vc0 < 32) ? Uf : Uh;
    const int c0 = j0 + (vc0 & 31);
    u64 uu[32];
#pragma unroll
    for (int i = 0; i < 32; i++)
        uu[i] = *(const u64*)&Usrc[(size_t)(kb + i) * H_SZ + c0];
    const float aP = pa[0];

    const unsigned sH_a = smem_u32(&sHp[0][0]);
    const unsigned mb_a = smem_u32(&mbar[0][0]);

    // Zero buffer 0 (step-0 h = 0); init barriers; pre-post expects for buf 1.
    sHp[0][tid] = make_float4(0.f, 0.f, 0.f, 0.f);
    if (tid == 0) {
#pragma unroll
        for (int s = 0; s < 2 * CPG; s++)
            asm volatile("mbarrier.init.shared.b64 [%0], 1;"
                         :: "r"(mb_a + 8u * s) : "memory");
#pragma unroll
        for (int s = 0; s < CPG; s++)   // buffer 1 first fill (sent at end of t=0)
            asm volatile("mbarrier.arrive.expect_tx.shared.b64 _, [%0], %1;"
                         :: "r"(mb_a + 8u * (CPG + s)), "r"(512u) : "memory");
    }
    __syncthreads();
    asm volatile("barrier.cluster.arrive.aligned;" ::: "memory");
    asm volatile("barrier.cluster.wait.aligned;" ::: "memory");

    // All-rank remote addresses, staggered start (r -> rank (cgi+r)&7).
    unsigned rbase[CPG], rmb[CPG];
#pragma unroll
    for (int r = 0; r < CPG; r++) {
        const unsigned rr = (cgi + (unsigned)r) & 7u;
        asm("mapa.shared::cluster.u32 %0, %1, %2;" : "=r"(rbase[r]) : "r"(sH_a), "r"(rr));
        asm("mapa.shared::cluster.u32 %0, %1, %2;" : "=r"(rmb[r])  : "r"(mb_a), "r"(rr));
    }

    const int ecol = tid & 31;
    const int eb   = tid >> 5;                // batch (valid for tid < 64)

    // Deep prefetch: xf/xh for step t are loaded at the top of step t-1.
    const size_t xstride = (size_t)B_SZ * 512;
    const size_t xbase0  = ((size_t)(g * NB + eb)) * 512 + j0 + ecol;
    float xfv = 0.f, xhv = 0.f;
    if (tid < 64) {
        xfv = g_xfh[xbase0];          // t = 0
        xhv = g_xfh[xbase0 + 256];
    }

    int par[2] = {0, 0};

    for (int t = 0; t < T_LEN; t++) {
        const int b = t & 1;

        // Issue NEXT step's xf/xh loads now (~full step of latency cover).
        float xfn = 0.f, xhn = 0.f;
        if (tid < 64) {
            const size_t tt = (t + 1 < T_LEN) ? (size_t)(t + 1) : (size_t)t;
            xfn = g_xfh[tt * xstride + xbase0];
            xhn = g_xfh[tt * xstride + xbase0 + 256];
        }

        if (t > 0) {   // warp w waits ONLY for its own source chunk
            const unsigned mb = mb_a + 8u * (unsigned)(b * CPG + w);
            asm volatile(
                "{\n\t .reg .pred p;\n\t"
                "LW%=:\n\t"
                "mbarrier.try_wait.parity.acquire.cluster.shared::cta.b64 p, [%0], %1, 0x989680;\n\t"
                "@!p bra LW%=;\n\t}"
                :: "r"(mb), "r"((unsigned)par[b]) : "memory");
            par[b] ^= 1;
        }

        const float4* __restrict__ hR = &sHp[b][0];

        u64 a0 = 0ull, a1 = 0ull;   // (c0,c1) partials for batch 0 / batch 1
#pragma unroll
        for (int i = 0; i < 32; i++) {
            ulonglong2 hp = *(const ulonglong2*)&hR[kb + i];  // (h0,h0),(h1,h1)
            fma2(a0, uu[i], hp.x);
            fma2(a1, uu[i], hp.y);
        }
        {
            float2 p0 = u2f(a0), p1 = u2f(a1);
            float* r0 = &sRed[b][vc0 * 17 + w];
            float* r1 = &sRed[b][(vc0 + 1) * 17 + w];
            r0[0] = p0.x;  r1[0] = p0.y;
            r0[8] = p1.x;  r1[8] = p1.y;
        }
        __syncthreads();   // ALL warps, every iter: partials + chunks visible

        // Warps 2-7: free-run to next step's mbarrier wait. Safe: sRed/sHp[b]
        // rewrites at t+2 are gated through peers' t+1 sends <= my t sends
        // <= bar.sync 3 below <= warps 0-1's reads this step.
        if (tid >= 64) continue;

        // Post expects for buffer b's NEXT fill before our sends (ordered by
        // bar.sync 3 below). Skip last two steps -> barriers end clean.
        if (tid < 8 && t < T_LEN - 2)
            asm volatile("mbarrier.arrive.expect_tx.shared.b64 _, [%0], %1;"
                         :: "r"(mb_a + 8u * (unsigned)(b * CPG + tid)), "r"(512u)
                         : "memory");

        const int sb = (t + 1) & 1;   // staging/send buffer
        float hv;
        {
            const float* rf = &sRed[b][ecol * 17 + eb * 8];
            const float* rh = &sRed[b][(ecol + 32) * 17 + eb * 8];
            float pf = ((rf[0] + rf[1]) + (rf[2] + rf[3]))
                     + ((rf[4] + rf[5]) + (rf[6] + rf[7])) + xfv;
            float ph = ((rh[0] + rh[1]) + (rh[2] + rh[3]))
                     + ((rh[4] + rh[5]) + (rh[6] + rh[7])) + xhv;

            float f  = fast_sigmoid(pf);
            float hn = fast_tanh(ph);
            float ho = ((const float*)&hR[j0 + ecol])[eb * 2];
            hv = f * ho + (1.0f - f) * hn;
            hv = (hv >= 0.0f) ? hv : aP * hv;

            // Duplicated staging: (h, h) at [col*4 + b*2 .. +1].
            sOut[sb][ecol * 4 + eb * 2]     = hv;
            sOut[sb][ecol * 4 + eb * 2 + 1] = hv;
        }
        // Fixed-membership barrier: warps 0-1, every iteration.
        asm volatile("bar.sync 3, 64;" ::: "memory");

        if (t < T_LEN - 1) {
            // Lane l of warp e sends slice l (16 B) to peers 4e..4e+3.
            ulonglong2 pay = *(const ulonglong2*)&sOut[sb][ecol * 4];
            const unsigned doff = (unsigned)sb * 4096u + cgi * 512u
                                + (unsigned)ecol * 16u;
            const unsigned mbo  = 8u * ((unsigned)sb * CPG + cgi);
            const int rb = eb * 4;
#pragma unroll
            for (int r = 0; r < 4; r++) {
                asm volatile(
                    "st.async.shared::cluster.mbarrier::complete_tx::bytes.v2.b64 "
                    "[%0], {%1, %2}, [%3];"
                    :: "r"(rbase[rb + r] + doff), "l"(pay.x), "l"(pay.y),
                       "r"(rmb[rb + r] + mbo)
                    : "memory");
            }
        }
        // Global store off the critical path (after send issue).
        out[((size_t)t * B_SZ + g * NB + eb) * H_SZ + j0 + ecol] = hv;

        xfv = xfn;
        xhv = xhn;
    }

    asm volatile("barrier.cluster.arrive.aligned;" ::: "memory");
    asm volatile("barrier.cluster.wait.aligned;" ::: "memory");
    if (tid == 0) {   // leave raw memory for next graph replay's init
#pragma unroll
        for (int s = 0; s < 2 * CPG; s++)
            asm volatile("mbarrier.inval.shared.b64 [%0];"
                         :: "r"(mb_a + 8u * s) : "memory");
    }
}

// ---------------- launch ------------------------------------------------------
extern "C" void kernel_launch(void* const* d_in, const int* in_sizes, int n_in,
                              void* d_out, int out_size) {
    (void)in_sizes; (void)n_in; (void)out_size;
    const float* seq = (const float*)d_in[0];
    const float* Wf  = (const float*)d_in[1];
    const float* Uf  = (const float*)d_in[2];
    const float* bf  = (const float*)d_in[3];
    const float* Wh  = (const float*)d_in[4];
    const float* Uh  = (const float*)d_in[5];
    const float* bh  = (const float*)d_in[6];
    const float* pa  = (const float*)d_in[7];
    float* out = (float*)d_out;

    dim3 pgrid(T_LEN * B_SZ / 128, 4);
    proj_kernel<<<pgrid, 256>>>(seq, Wf, bf, Wh, bh);

    rec_kernel<<<NGRP * CPG, 256>>>(Uf, Uh, pa, out);
}

// round 16
// speedup vs baseline: 1.2073x; 1.0467x over previous
#include <cuda_runtime.h>
#include <math.h>

#define T_LEN 2048
#define B_SZ  64
#define I_SZ  256
#define H_SZ  256

#define NGRP 32
#define CPG  8     // CTAs per group = cluster size
#define NB   2     // batches per group

typedef unsigned long long u64;

__device__ __forceinline__ void fma2(u64 &d, u64 a, u64 b) {
    asm("fma.rn.f32x2 %0, %1, %2, %0;" : "+l"(d) : "l"(a), "l"(b));
}
__device__ __forceinline__ float2 u2f(u64 v) {
    float2 r; asm("mov.b64 {%0, %1}, %2;" : "=f"(r.x), "=f"(r.y) : "l"(v)); return r;
}
__device__ __forceinline__ u64 dup2(float x) {
    u64 r; asm("mov.b64 %0, {%1, %1};" : "=l"(r) : "f"(x)); return r;
}
__device__ __forceinline__ unsigned smem_u32(const void* p) {
    unsigned a;
    asm("{ .reg .u64 t; cvta.to.shared.u64 t, %1; cvt.u32.u64 %0, t; }" : "=r"(a) : "l"(p));
    return a;
}
// Fast sigmoid / tanh via ex2.approx + rcp.approx (rel err ~2^-22).
__device__ __forceinline__ float fast_sigmoid(float x) {
    x = fminf(fmaxf(x, -20.f), 20.f);
    float e, r;
    asm("ex2.approx.f32 %0, %1;" : "=f"(e) : "f"(-x * 1.4426950408889634f));
    asm("rcp.approx.f32 %0, %1;" : "=f"(r) : "f"(e + 1.0f));
    return r;
}
__device__ __forceinline__ float fast_tanh(float x) {
    x = fminf(fmaxf(x, -15.f), 15.f);
    float e, r;
    asm("ex2.approx.f32 %0, %1;" : "=f"(e) : "f"(x * 2.8853900817779268f));  // e^{2x}
    asm("rcp.approx.f32 %0, %1;" : "=f"(r) : "f"(e + 1.0f));
    return (e - 1.0f) * r;
}

// ---------------- scratch ----------------------------------------------------
__device__ float g_xfh[(size_t)T_LEN * B_SZ * 512];   // [t][b][0:256]=xf, [256:512]=xh

// ---------------- projection GEMM (double-buffered, natural A + reg dup) -----
__global__ __launch_bounds__(256) void proj_kernel(
    const float* __restrict__ seq,
    const float* __restrict__ Wf, const float* __restrict__ bf,
    const float* __restrict__ Wh, const float* __restrict__ bh)
{
    __shared__ float As[2][8][132];
    __shared__ float Bs[2][8][132];

    const int bm = blockIdx.x;
    const int bn = blockIdx.y;
    const float* __restrict__ W    = (bn < 2) ? Wf : Wh;
    const float* __restrict__ bias = (bn < 2) ? bf : bh;
    const int nb = (bn & 1) * 128;

    const int tid  = threadIdx.x;
    const int tx   = tid & 15;
    const int ty   = tid >> 4;
    const int arow = tid >> 1, acol = (tid & 1) * 4;
    const int brow = tid >> 5, bcol = (tid & 31) * 4;
    const size_t abase = (size_t)(bm * 128 + arow) * 256 + acol;

    u64 acc[8][4];
#pragma unroll
    for (int i = 0; i < 8; i++)
#pragma unroll
        for (int j = 0; j < 4; j++) acc[i][j] = 0ull;

    {
        float4 av = *(const float4*)&seq[abase];
        float4 bv = *(const float4*)&W[(size_t)brow * 256 + nb + bcol];
        As[0][acol + 0][arow] = av.x;
        As[0][acol + 1][arow] = av.y;
        As[0][acol + 2][arow] = av.z;
        As[0][acol + 3][arow] = av.w;
        *(float4*)&Bs[0][brow][bcol] = bv;
    }
    __syncthreads();

    for (int it = 0; it < 32; it++) {
        const int p = it & 1;
        float4 av, bv;
        if (it < 31) {
            const int k0 = (it + 1) * 8;
            av = *(const float4*)&seq[abase + k0];
            bv = *(const float4*)&W[(size_t)(k0 + brow) * 256 + nb + bcol];
        }
#pragma unroll
        for (int k = 0; k < 8; k++) {
            float4 aA = *(const float4*)&As[p][k][ty * 8];
            float4 aB = *(const float4*)&As[p][k][ty * 8 + 4];
            ulonglong2 b01 = *(const ulonglong2*)&Bs[p][k][tx * 8];
            ulonglong2 b23 = *(const ulonglong2*)&Bs[p][k][tx * 8 + 4];
            u64 ad[8];
            ad[0] = dup2(aA.x); ad[1] = dup2(aA.y);
            ad[2] = dup2(aA.z); ad[3] = dup2(aA.w);
            ad[4] = dup2(aB.x); ad[5] = dup2(aB.y);
            ad[6] = dup2(aB.z); ad[7] = dup2(aB.w);
#pragma unroll
            for (int i = 0; i < 8; i++) {
                fma2(acc[i][0], ad[i], b01.x);
                fma2(acc[i][1], ad[i], b01.y);
                fma2(acc[i][2], ad[i], b23.x);
                fma2(acc[i][3], ad[i], b23.y);
            }
        }
        if (it < 31) {
            const int np = p ^ 1;
            As[np][acol + 0][arow] = av.x;
            As[np][acol + 1][arow] = av.y;
            As[np][acol + 2][arow] = av.z;
            As[np][acol + 3][arow] = av.w;
            *(float4*)&Bs[np][brow][bcol] = bv;
        }
        __syncthreads();
    }

    float bb[8];
#pragma unroll
    for (int j = 0; j < 8; j++) bb[j] = bias[nb + tx * 8 + j];

#pragma unroll
    for (int i = 0; i < 8; i++) {
        size_t m = (size_t)bm * 128 + ty * 8 + i;
        float* op = &g_xfh[m * 512 + (size_t)bn * 128 + tx * 8];
        float2 c0 = u2f(acc[i][0]), c1 = u2f(acc[i][1]);
        float2 c2 = u2f(acc[i][2]), c3 = u2f(acc[i][3]);
        float4 v0, v1;
        v0.x = c0.x + bb[0]; v0.y = c0.y + bb[1];
        v0.z = c1.x + bb[2]; v0.w = c1.y + bb[3];
        v1.x = c2.x + bb[4]; v1.y = c2.y + bb[5];
        v1.z = c3.x + bb[6]; v1.w = c3.y + bb[7];
        *(float4*)&op[0] = v0;
        *(float4*)&op[4] = v1;
    }
}

// ---------------- persistent recurrence: 32 groups x 2 batches ---------------
// R15 EXACT (best passing): sRed double-buffered; warps 2-7 free-run; warps
// 0-1 epilogue behind fixed-membership bar.sync 3,64; split send duty.
__global__ __launch_bounds__(256, 2) __cluster_dims__(CPG, 1, 1)
void rec_kernel(const float* __restrict__ Uf, const float* __restrict__ Uh,
                const float* __restrict__ pa, float* __restrict__ out)
{
    __shared__ float4 sHp[2][256];                     // 8 KB recv: [buf][k]=(h0,h0,h1,h1)
    __shared__ float  sRed[2][64 * 17];                // 8.7 KB: [buf][vc*17 + b*8 + w]
    __shared__ __align__(16) float sOut[2][128];       // 1 KB staging: [buf][col*4+b*2+d]
    __shared__ __align__(16) u64 mbar[2][CPG];         // per-buffer, per-source

    const int g   = blockIdx.x >> 3;                   // 0..31
    unsigned cgi;
    asm("mov.u32 %0, %%cluster_ctarank;" : "=r"(cgi));
    const int j0  = (int)cgi * 32;
    const int tid = threadIdx.x;
    const int w   = tid >> 5;
    const int l   = tid & 31;
    const int kb  = w * 32;
    const int vc0 = 2 * l;

    // Register-resident U as NATURAL (c0,c1) pairs: 32 x u64 per thread.
    const float* __restrict__ Usrc = (vc0 < 32) ? Uf : Uh;
    const int c0 = j0 + (vc0 & 31);
    u64 uu[32];
#pragma unroll
    for (int i = 0; i < 32; i++)
        uu[i] = *(const u64*)&Usrc[(size_t)(kb + i) * H_SZ + c0];
    const float aP = pa[0];

    const unsigned sH_a = smem_u32(&sHp[0][0]);
    const unsigned mb_a = smem_u32(&mbar[0][0]);

    // Zero buffer 0 (step-0 h = 0); init barriers; pre-post expects for buf 1.
    sHp[0][tid] = make_float4(0.f, 0.f, 0.f, 0.f);
    if (tid == 0) {
#pragma unroll
        for (int s = 0; s < 2 * CPG; s++)
            asm volatile("mbarrier.init.shared.b64 [%0], 1;"
                         :: "r"(mb_a + 8u * s) : "memory");
#pragma unroll
        for (int s = 0; s < CPG; s++)   // buffer 1 first fill (sent at end of t=0)
            asm volatile("mbarrier.arrive.expect_tx.shared.b64 _, [%0], %1;"
                         :: "r"(mb_a + 8u * (CPG + s)), "r"(512u) : "memory");
    }
    __syncthreads();
    asm volatile("barrier.cluster.arrive.aligned;" ::: "memory");
    asm volatile("barrier.cluster.wait.aligned;" ::: "memory");

    // All-rank remote addresses, staggered start (r -> rank (cgi+r)&7).
    unsigned rbase[CPG], rmb[CPG];
#pragma unroll
    for (int r = 0; r < CPG; r++) {
        const unsigned rr = (cgi + (unsigned)r) & 7u;
        asm("mapa.shared::cluster.u32 %0, %1, %2;" : "=r"(rbase[r]) : "r"(sH_a), "r"(rr));
        asm("mapa.shared::cluster.u32 %0, %1, %2;" : "=r"(rmb[r])  : "r"(mb_a), "r"(rr));
    }

    const int ecol = tid & 31;
    const int eb   = tid >> 5;                // batch (valid for tid < 64)

    // Deep prefetch: xf/xh for step t are loaded at the top of step t-1.
    const size_t xstride = (size_t)B_SZ * 512;
    const size_t xbase0  = ((size_t)(g * NB + eb)) * 512 + j0 + ecol;
    float xfv = 0.f, xhv = 0.f;
    if (tid < 64) {
        xfv = g_xfh[xbase0];          // t = 0
        xhv = g_xfh[xbase0 + 256];
    }

    int par[2] = {0, 0};

    for (int t = 0; t < T_LEN; t++) {
        const int b = t & 1;

        // Issue NEXT step's xf/xh loads now (~full step of latency cover).
        float xfn = 0.f, xhn = 0.f;
        if (tid < 64) {
            const size_t tt = (t + 1 < T_LEN) ? (size_t)(t + 1) : (size_t)t;
            xfn = g_xfh[tt * xstride + xbase0];
            xhn = g_xfh[tt * xstride + xbase0 + 256];
        }

        if (t > 0) {   // warp w waits ONLY for its own source chunk
            const unsigned mb = mb_a + 8u * (unsigned)(b * CPG + w);
            asm volatile(
                "{\n\t .reg .pred p;\n\t"
                "LW%=:\n\t"
                "mbarrier.try_wait.parity.acquire.cluster.shared::cta.b64 p, [%0], %1, 0x989680;\n\t"
                "@!p bra LW%=;\n\t}"
                :: "r"(mb), "r"((unsigned)par[b]) : "memory");
            par[b] ^= 1;
        }

        const float4* __restrict__ hR = &sHp[b][0];

        u64 a0 = 0ull, a1 = 0ull;   // (c0,c1) partials for batch 0 / batch 1
#pragma unroll
        for (int i = 0; i < 32; i++) {
            ulonglong2 hp = *(const ulonglong2*)&hR[kb + i];  // (h0,h0),(h1,h1)
            fma2(a0, uu[i], hp.x);
            fma2(a1, uu[i], hp.y);
        }
        {
            float2 p0 = u2f(a0), p1 = u2f(a1);
            float* r0 = &sRed[b][vc0 * 17 + w];
            float* r1 = &sRed[b][(vc0 + 1) * 17 + w];
            r0[0] = p0.x;  r1[0] = p0.y;
            r0[8] = p1.x;  r1[8] = p1.y;
        }
        __syncthreads();   // ALL warps, every iter: partials + chunks visible

        // Warps 2-7: free-run to next step's mbarrier wait. Safe: sRed/sHp[b]
        // rewrites at t+2 are gated through peers' t+1 sends <= my t sends
        // <= bar.sync 3 below <= warps 0-1's reads this step.
        if (tid >= 64) continue;

        // Post expects for buffer b's NEXT fill before our sends (ordered by
        // bar.sync 3 below). Skip last two steps -> barriers end clean.
        if (tid < 8 && t < T_LEN - 2)
            asm volatile("mbarrier.arrive.expect_tx.shared.b64 _, [%0], %1;"
                         :: "r"(mb_a + 8u * (unsigned)(b * CPG + tid)), "r"(512u)
                         : "memory");

        const int sb = (t + 1) & 1;   // staging/send buffer
        float hv;
        {
            const float* rf = &sRed[b][ecol * 17 + eb * 8];
            const float* rh = &sRed[b][(ecol + 32) * 17 + eb * 8];
            float pf = ((rf[0] + rf[1]) + (rf[2] + rf[3]))
                     + ((rf[4] + rf[5]) + (rf[6] + rf[7])) + xfv;
            float ph = ((rh[0] + rh[1]) + (rh[2] + rh[3]))
                     + ((rh[4] + rh[5]) + (rh[6] + rh[7])) + xhv;

            float f  = fast_sigmoid(pf);
            float hn = fast_tanh(ph);
            float ho = ((const float*)&hR[j0 + ecol])[eb * 2];
            hv = f * ho + (1.0f - f) * hn;
            hv = (hv >= 0.0f) ? hv : aP * hv;

            // Duplicated staging: (h, h) at [col*4 + b*2 .. +1].
            sOut[sb][ecol * 4 + eb * 2]     = hv;
            sOut[sb][ecol * 4 + eb * 2 + 1] = hv;
        }
        // Fixed-membership barrier: warps 0-1, every iteration.
        asm volatile("bar.sync 3, 64;" ::: "memory");

        if (t < T_LEN - 1) {
            // Lane l of warp e sends slice l (16 B) to peers 4e..4e+3.
            ulonglong2 pay = *(const ulonglong2*)&sOut[sb][ecol * 4];
            const unsigned doff = (unsigned)sb * 4096u + cgi * 512u
                                + (unsigned)ecol * 16u;
            const unsigned mbo  = 8u * ((unsigned)sb * CPG + cgi);
            const int rb = eb * 4;
#pragma unroll
            for (int r = 0; r < 4; r++) {
                asm volatile(
                    "st.async.shared::cluster.mbarrier::complete_tx::bytes.v2.b64 "
                    "[%0], {%1, %2}, [%3];"
                    :: "r"(rbase[rb + r] + doff), "l"(pay.x), "l"(pay.y),
                       "r"(rmb[rb + r] + mbo)
                    : "memory");
            }
        }
        // Global store off the critical path (after send issue).
        out[((size_t)t * B_SZ + g * NB + eb) * H_SZ + j0 + ecol] = hv;

        xfv = xfn;
        xhv = xhn;
    }

    asm volatile("barrier.cluster.arrive.aligned;" ::: "memory");
    asm volatile("barrier.cluster.wait.aligned;" ::: "memory");
    if (tid == 0) {   // leave raw memory for next graph replay's init
#pragma unroll
        for (int s = 0; s < 2 * CPG; s++)
            asm volatile("mbarrier.inval.shared.b64 [%0];"
                         :: "r"(mb_a + 8u * s) : "memory");
    }
}

// ---------------- launch ------------------------------------------------------
extern "C" void kernel_launch(void* const* d_in, const int* in_sizes, int n_in,
                              void* d_out, int out_size) {
    (void)in_sizes; (void)n_in; (void)out_size;
    const float* seq = (const float*)d_in[0];
    const float* Wf  = (const float*)d_in[1];
    const float* Uf  = (const float*)d_in[2];
    const float* bf  = (const float*)d_in[3];
    const float* Wh  = (const float*)d_in[4];
    const float* Uh  = (const float*)d_in[5];
    const float* bh  = (const float*)d_in[6];
    const float* pa  = (const float*)d_in[7];
    float* out = (float*)d_out;

    dim3 pgrid(T_LEN * B_SZ / 128, 4);
    proj_kernel<<<pgrid, 256>>>(seq, Wf, bf, Wh, bh);

    rec_kernel<<<NGRP * CPG, 256>>>(Uf, Uh, pa, out);
}

// round 17
// speedup vs baseline: 1.3819x; 1.1446x over previous
#include <cuda_runtime.h>
#include <math.h>

#define T_LEN 2048
#define B_SZ  64
#define I_SZ  256
#define H_SZ  256

#define NGRP 32
#define CPG  8     // CTAs per group = cluster size
#define NB   2     // batches per group

typedef unsigned long long u64;

__device__ __forceinline__ void fma2(u64 &d, u64 a, u64 b) {
    asm("fma.rn.f32x2 %0, %1, %2, %0;" : "+l"(d) : "l"(a), "l"(b));
}
__device__ __forceinline__ float2 u2f(u64 v) {
    float2 r; asm("mov.b64 {%0, %1}, %2;" : "=f"(r.x), "=f"(r.y) : "l"(v)); return r;
}
__device__ __forceinline__ u64 dup2(float x) {
    u64 r; asm("mov.b64 %0, {%1, %1};" : "=l"(r) : "f"(x)); return r;
}
__device__ __forceinline__ u64 pack2(float x, float y) {
    u64 r; asm("mov.b64 %0, {%1, %2};" : "=l"(r) : "f"(x), "f"(y)); return r;
}
__device__ __forceinline__ unsigned smem_u32(const void* p) {
    unsigned a;
    asm("{ .reg .u64 t; cvta.to.shared.u64 t, %1; cvt.u32.u64 %0, t; }" : "=r"(a) : "l"(p));
    return a;
}
// Fast sigmoid / tanh via ex2.approx + rcp.approx (rel err ~2^-22).
__device__ __forceinline__ float fast_sigmoid(float x) {
    x = fminf(fmaxf(x, -20.f), 20.f);
    float e, r;
    asm("ex2.approx.f32 %0, %1;" : "=f"(e) : "f"(-x * 1.4426950408889634f));
    asm("rcp.approx.f32 %0, %1;" : "=f"(r) : "f"(e + 1.0f));
    return r;
}
__device__ __forceinline__ float fast_tanh(float x) {
    x = fminf(fmaxf(x, -15.f), 15.f);
    float e, r;
    asm("ex2.approx.f32 %0, %1;" : "=f"(e) : "f"(x * 2.8853900817779268f));  // e^{2x}
    asm("rcp.approx.f32 %0, %1;" : "=f"(r) : "f"(e + 1.0f));
    return (e - 1.0f) * r;
}

// ---------------- scratch ----------------------------------------------------
__device__ float g_xfh[(size_t)T_LEN * B_SZ * 512];   // [t][b][0:256]=xf, [256:512]=xh

// ---------------- projection GEMM (double-buffered, natural A + reg dup) -----
__global__ __launch_bounds__(256) void proj_kernel(
    const float* __restrict__ seq,
    const float* __restrict__ Wf, const float* __restrict__ bf,
    const float* __restrict__ Wh, const float* __restrict__ bh)
{
    __shared__ float As[2][8][132];
    __shared__ float Bs[2][8][132];

    const int bm = blockIdx.x;
    const int bn = blockIdx.y;
    const float* __restrict__ W    = (bn < 2) ? Wf : Wh;
    const float* __restrict__ bias = (bn < 2) ? bf : bh;
    const int nb = (bn & 1) * 128;

    const int tid  = threadIdx.x;
    const int tx   = tid & 15;
    const int ty   = tid >> 4;
    const int arow = tid >> 1, acol = (tid & 1) * 4;
    const int brow = tid >> 5, bcol = (tid & 31) * 4;
    const size_t abase = (size_t)(bm * 128 + arow) * 256 + acol;

    u64 acc[8][4];
#pragma unroll
    for (int i = 0; i < 8; i++)
#pragma unroll
        for (int j = 0; j < 4; j++) acc[i][j] = 0ull;

    {
        float4 av = *(const float4*)&seq[abase];
        float4 bv = *(const float4*)&W[(size_t)brow * 256 + nb + bcol];
        As[0][acol + 0][arow] = av.x;
        As[0][acol + 1][arow] = av.y;
        As[0][acol + 2][arow] = av.z;
        As[0][acol + 3][arow] = av.w;
        *(float4*)&Bs[0][brow][bcol] = bv;
    }
    __syncthreads();

    for (int it = 0; it < 32; it++) {
        const int p = it & 1;
        float4 av, bv;
        if (it < 31) {
            const int k0 = (it + 1) * 8;
            av = *(const float4*)&seq[abase + k0];
            bv = *(const float4*)&W[(size_t)(k0 + brow) * 256 + nb + bcol];
        }
#pragma unroll
        for (int k = 0; k < 8; k++) {
            float4 aA = *(const float4*)&As[p][k][ty * 8];
            float4 aB = *(const float4*)&As[p][k][ty * 8 + 4];
            ulonglong2 b01 = *(const ulonglong2*)&Bs[p][k][tx * 8];
            ulonglong2 b23 = *(const ulonglong2*)&Bs[p][k][tx * 8 + 4];
            u64 ad[8];
            ad[0] = dup2(aA.x); ad[1] = dup2(aA.y);
            ad[2] = dup2(aA.z); ad[3] = dup2(aA.w);
            ad[4] = dup2(aB.x); ad[5] = dup2(aB.y);
            ad[6] = dup2(aB.z); ad[7] = dup2(aB.w);
#pragma unroll
            for (int i = 0; i < 8; i++) {
                fma2(acc[i][0], ad[i], b01.x);
                fma2(acc[i][1], ad[i], b01.y);
                fma2(acc[i][2], ad[i], b23.x);
                fma2(acc[i][3], ad[i], b23.y);
            }
        }
        if (it < 31) {
            const int np = p ^ 1;
            As[np][acol + 0][arow] = av.x;
            As[np][acol + 1][arow] = av.y;
            As[np][acol + 2][arow] = av.z;
            As[np][acol + 3][arow] = av.w;
            *(float4*)&Bs[np][brow][bcol] = bv;
        }
        __syncthreads();
    }

    float bb[8];
#pragma unroll
    for (int j = 0; j < 8; j++) bb[j] = bias[nb + tx * 8 + j];

#pragma unroll
    for (int i = 0; i < 8; i++) {
        size_t m = (size_t)bm * 128 + ty * 8 + i;
        float* op = &g_xfh[m * 512 + (size_t)bn * 128 + tx * 8];
        float2 c0 = u2f(acc[i][0]), c1 = u2f(acc[i][1]);
        float2 c2 = u2f(acc[i][2]), c3 = u2f(acc[i][3]);
        float4 v0, v1;
        v0.x = c0.x + bb[0]; v0.y = c0.y + bb[1];
        v0.z = c1.x + bb[2]; v0.w = c1.y + bb[3];
        v1.x = c2.x + bb[4]; v1.y = c2.y + bb[5];
        v1.z = c3.x + bb[6]; v1.w = c3.y + bb[7];
        *(float4*)&op[0] = v0;
        *(float4*)&op[4] = v1;
    }
}

// ---------------- persistent recurrence: 32 groups x 2 batches ---------------
// R15 skeleton; exchange switched to k-natural per-batch layout sHb[b][k]
// with k-paired U registers: half the DSMEM payload (256 B/source), half the
// messages (16/source), half the inner-loop LDS bytes, identical issue count.
__global__ __launch_bounds__(256, 2) __cluster_dims__(CPG, 1, 1)
void rec_kernel(const float* __restrict__ Uf, const float* __restrict__ Uh,
                const float* __restrict__ pa, float* __restrict__ out)
{
    __shared__ float sHb[2][2][256];                   // 4 KB recv: [buf][batch][k]
    __shared__ float sRed[2][64 * 17];                 // 8.7 KB: [buf][vc*17 + b*8 + w]
    __shared__ __align__(16) float sOut[2][64];        // 512 B staging: [buf][b*32+col]
    __shared__ __align__(16) u64 mbar[2][CPG];         // per-buffer, per-source

    const int g   = blockIdx.x >> 3;                   // 0..31
    unsigned cgi;
    asm("mov.u32 %0, %%cluster_ctarank;" : "=r"(cgi));
    const int j0  = (int)cgi * 32;
    const int tid = threadIdx.x;
    const int w   = tid >> 5;
    const int l   = tid & 31;
    const int kb  = w * 32;
    const int vc0 = 2 * l;

    // Register-resident U, K-PAIRED per column: uc0/uc1[i] = (U[kb+2i][c], U[kb+2i+1][c]).
    const float* __restrict__ Usrc = (vc0 < 32) ? Uf : Uh;
    const int c0 = j0 + (vc0 & 31);
    u64 uc0[16], uc1[16];
#pragma unroll
    for (int i = 0; i < 16; i++) {
        const float* r0 = &Usrc[(size_t)(kb + 2 * i) * H_SZ + c0];
        const float* r1 = &Usrc[(size_t)(kb + 2 * i + 1) * H_SZ + c0];
        uc0[i] = pack2(r0[0], r1[0]);
        uc1[i] = pack2(r0[1], r1[1]);
    }
    const float aP = pa[0];

    const unsigned sH_a = smem_u32(&sHb[0][0][0]);
    const unsigned mb_a = smem_u32(&mbar[0][0]);

    // Zero buffer 0 (step-0 h = 0, both batches); init barriers; pre-post buf 1.
    if (tid < 128) ((float4*)&sHb[0][0][0])[tid] = make_float4(0.f, 0.f, 0.f, 0.f);
    if (tid == 0) {
#pragma unroll
        for (int s = 0; s < 2 * CPG; s++)
            asm volatile("mbarrier.init.shared.b64 [%0], 1;"
                         :: "r"(mb_a + 8u * s) : "memory");
#pragma unroll
        for (int s = 0; s < CPG; s++)   // buffer 1 first fill (sent at end of t=0)
            asm volatile("mbarrier.arrive.expect_tx.shared.b64 _, [%0], %1;"
                         :: "r"(mb_a + 8u * (CPG + s)), "r"(256u) : "memory");
    }
    __syncthreads();
    asm volatile("barrier.cluster.arrive.aligned;" ::: "memory");
    asm volatile("barrier.cluster.wait.aligned;" ::: "memory");

    // All-rank remote addresses, staggered start (r -> rank (cgi+r)&7).
    unsigned rbase[CPG], rmb[CPG];
#pragma unroll
    for (int r = 0; r < CPG; r++) {
        const unsigned rr = (cgi + (unsigned)r) & 7u;
        asm("mapa.shared::cluster.u32 %0, %1, %2;" : "=r"(rbase[r]) : "r"(sH_a), "r"(rr));
        asm("mapa.shared::cluster.u32 %0, %1, %2;" : "=r"(rmb[r])  : "r"(mb_a), "r"(rr));
    }

    const int ecol = tid & 31;
    const int eb   = tid >> 5;                // batch (valid for tid < 64)

    // Deep prefetch: xf/xh for step t are loaded at the top of step t-1.
    const size_t xstride = (size_t)B_SZ * 512;
    const size_t xbase0  = ((size_t)(g * NB + eb)) * 512 + j0 + ecol;
    float xfv = 0.f, xhv = 0.f;
    if (tid < 64) {
        xfv = g_xfh[xbase0];          // t = 0
        xhv = g_xfh[xbase0 + 256];
    }

    int par[2] = {0, 0};

    for (int t = 0; t < T_LEN; t++) {
        const int b = t & 1;

        // Issue NEXT step's xf/xh loads now (~full step of latency cover).
        float xfn = 0.f, xhn = 0.f;
        if (tid < 64) {
            const size_t tt = (t + 1 < T_LEN) ? (size_t)(t + 1) : (size_t)t;
            xfn = g_xfh[tt * xstride + xbase0];
            xhn = g_xfh[tt * xstride + xbase0 + 256];
        }

        if (t > 0) {   // warp w waits ONLY for its own source chunk
            const unsigned mb = mb_a + 8u * (unsigned)(b * CPG + w);
            asm volatile(
                "{\n\t .reg .pred p;\n\t"
                "LW%=:\n\t"
                "mbarrier.try_wait.parity.acquire.cluster.shared::cta.b64 p, [%0], %1, 0x989680;\n\t"
                "@!p bra LW%=;\n\t}"
                :: "r"(mb), "r"((unsigned)par[b]) : "memory");
            par[b] ^= 1;
        }

        const float* __restrict__ h0R = &sHb[b][0][0];
        const float* __restrict__ h1R = &sHb[b][1][0];

        u64 a00 = 0ull, a01v = 0ull, a10 = 0ull, a11 = 0ull;
#pragma unroll
        for (int i = 0; i < 16; i++) {
            u64 hb0 = *(const u64*)&h0R[kb + 2 * i];   // (h_2i[0], h_2i+1[0])
            u64 hb1 = *(const u64*)&h1R[kb + 2 * i];   // (h_2i[1], h_2i+1[1])
            fma2(a00,  uc0[i], hb0);
            fma2(a01v, uc0[i], hb1);
            fma2(a10,  uc1[i], hb0);
            fma2(a11,  uc1[i], hb1);
        }
        {
            float2 q00 = u2f(a00), q01 = u2f(a01v), q10 = u2f(a10), q11 = u2f(a11);
            float* r0 = &sRed[b][vc0 * 17 + w];
            float* r1 = &sRed[b][(vc0 + 1) * 17 + w];
            r0[0] = q00.x + q00.y;  r0[8] = q01.x + q01.y;
            r1[0] = q10.x + q10.y;  r1[8] = q11.x + q11.y;
        }
        __syncthreads();   // ALL warps, every iter: partials + chunks visible

        // Warps 2-7: free-run to next step's mbarrier wait. Safe: sRed/sHb[b]
        // rewrites at t+2 are gated through peers' t+1 sends <= my t sends
        // <= bar.sync 3 below <= warps 0-1's reads this step.
        if (tid >= 64) continue;

        // Post expects for buffer b's NEXT fill before our sends (ordered by
        // bar.sync 3 below). Skip last two steps -> barriers end clean.
        if (tid < 8 && t < T_LEN - 2)
            asm volatile("mbarrier.arrive.expect_tx.shared.b64 _, [%0], %1;"
                         :: "r"(mb_a + 8u * (unsigned)(b * CPG + tid)), "r"(256u)
                         : "memory");

        const int sb = (t + 1) & 1;   // staging/send buffer
        float hv;
        {
            const float* rf = &sRed[b][ecol * 17 + eb * 8];
            const float* rh = &sRed[b][(ecol + 32) * 17 + eb * 8];
            float pf = ((rf[0] + rf[1]) + (rf[2] + rf[3]))
                     + ((rf[4] + rf[5]) + (rf[6] + rf[7])) + xfv;
            float ph = ((rh[0] + rh[1]) + (rh[2] + rh[3]))
                     + ((rh[4] + rh[5]) + (rh[6] + rh[7])) + xhv;

            float f  = fast_sigmoid(pf);
            float hn = fast_tanh(ph);
            float ho = sHb[b][eb][j0 + ecol];
            hv = f * ho + (1.0f - f) * hn;
            hv = (hv >= 0.0f) ? hv : aP * hv;

            sOut[sb][eb * 32 + ecol] = hv;   // natural per-batch staging
        }
        // Fixed-membership barrier: warps 0-1, every iteration.
        asm volatile("bar.sync 3, 64;" ::: "memory");

        if (t < T_LEN - 1) {
            // 16 msgs of 16 B per destination; warp e covers dests 4e..4e+3.
            // Lane l: msg m = l&15 (batch m>>3, col-group m&7), dest pair by l>>4.
            const int m   = l & 15;
            const int mb2 = m >> 3;          // batch of this message
            const int cg  = m & 7;           // col group (4 cols)
            ulonglong2 pay = *(const ulonglong2*)&sOut[sb][mb2 * 32 + cg * 4];
            const unsigned doff = (unsigned)sb * 2048u + (unsigned)mb2 * 1024u
                                + (cgi * 32u + (unsigned)cg * 4u) * 4u;
            const unsigned mbo  = 8u * ((unsigned)sb * CPG + cgi);
            const int rb = eb * 4 + (l >> 4) * 2;
#pragma unroll
            for (int r = 0; r < 2; r++) {
                asm volatile(
                    "st.async.shared::cluster.mbarrier::complete_tx::bytes.v2.b64 "
                    "[%0], {%1, %2}, [%3];"
                    :: "r"(rbase[rb + r] + doff), "l"(pay.x), "l"(pay.y),
                       "r"(rmb[rb + r] + mbo)
                    : "memory");
            }
        }
        // Global store off the critical path (after send issue).
        out[((size_t)t * B_SZ + g * NB + eb) * H_SZ + j0 + ecol] = hv;

        xfv = xfn;
        xhv = xhn;
    }

    asm volatile("barrier.cluster.arrive.aligned;" ::: "memory");
    asm volatile("barrier.cluster.wait.aligned;" ::: "memory");
    if (tid == 0) {   // leave raw memory for next graph replay's init
#pragma unroll
        for (int s = 0; s < 2 * CPG; s++)
            asm volatile("mbarrier.inval.shared.b64 [%0];"
                         :: "r"(mb_a + 8u * s) : "memory");
    }
}

// ---------------- launch ------------------------------------------------------
extern "C" void kernel_launch(void* const* d_in, const int* in_sizes, int n_in,
                              void* d_out, int out_size) {
    (void)in_sizes; (void)n_in; (void)out_size;
    const float* seq = (const float*)d_in[0];
    const float* Wf  = (const float*)d_in[1];
    const float* Uf  = (const float*)d_in[2];
    const float* bf  = (const float*)d_in[3];
    const float* Wh  = (const float*)d_in[4];
    const float* Uh  = (const float*)d_in[5];
    const float* bh  = (const float*)d_in[6];
    const float* pa  = (const float*)d_in[7];
    float* out = (float*)d_out;

    dim3 pgrid(T_LEN * B_SZ / 128, 4);
    proj_kernel<<<pgrid, 256>>>(seq, Wf, bf, Wh, bh);

    rec_kernel<<<NGRP * CPG, 256>>>(Uf, Uh, pa, out);
}